// round 15
// baseline (speedup 1.0000x reference)
#include <cuda_runtime.h>
#include <math.h>

// Fully fused single kernel, fast path with NO shared memory:
// uniform pilot grid (pilot_pos[k] = 1+8k, verified via broadcast loads)
// -> weights periodic with period 8 -> per-thread register coefficients;
// taps read directly from global with arithmetic addresses (broadcast
// LDG.64, L1-resident row), so there is no staging, no STS, and no
// memory-drain barrier before the first store issues.
// Generic fallback (non-uniform grid): stage knots in smem + binary search.

__device__ __forceinline__ unsigned long long pack2(float a, float b) {
    unsigned long long r;
    asm("mov.b64 %0, {%1, %2};" : "=l"(r) : "f"(a), "f"(b));
    return r;
}
__device__ __forceinline__ float2 unpack2(unsigned long long v) {
    float2 r;
    asm("mov.b64 {%0, %1}, %2;" : "=f"(r.x), "=f"(r.y) : "l"(v));
    return r;
}
__device__ __forceinline__ unsigned long long mul_f32x2(unsigned long long a,
                                                        unsigned long long b) {
    unsigned long long r;
    asm("mul.rn.f32x2 %0, %1, %2;" : "=l"(r) : "l"(a), "l"(b));
    return r;
}
__device__ __forceinline__ unsigned long long fma_f32x2(unsigned long long a,
                                                        unsigned long long b,
                                                        unsigned long long c) {
    unsigned long long r;
    asm("fma.rn.f32x2 %0, %1, %2, %3;" : "=l"(r) : "l"(a), "l"(b), "l"(c));
    return r;
}

__global__ void __launch_bounds__(256, 8)
interp_kernel(const float2* __restrict__ H,     // [B, NP]
              const float* __restrict__ pilot_pos,
              const float* __restrict__ decay_param,
              float* __restrict__ out,           // [B, Nfft, 2]
              int NP, int nf4, int Nfft) {       // nf4 = Nfft/2
    extern __shared__ float sLoc[];               // NP+2 (fallback only)

    const int tid = threadIdx.x;
    const int b   = blockIdx.x;

    const float2* Hrow = H + (size_t)b * NP;

    // Uniformity predicate: pilot_pos[k] == 1 + 8k (broadcast L1 hits).
    bool ok = (NP >= 3) && (8 * (NP - 1) < Nfft - 1);
    for (int k = tid; k < NP; k += 256)
        if (__ldg(pilot_pos + k) != 1.0f + 8.0f * (float)k) ok = false;

    float dp = __ldg(decay_param);
    float decay = (dp > 20.0f) ? dp : log1pf(expf(dp));

    // Cheap consensus barrier (no memory drain behind it).
    int unif = __syncthreads_and(ok ? 1 : 0);

    float4* orow = (float4*)out + (size_t)b * nf4;

    if (unif) {
        const int li    = 8 * (NP - 1);   // last pilot location (e.g. 4088)
        const int tailt = li >> 1;        // first tail f4 index

        // Register-resident coefficients for this thread's phase (tid&3).
        float d0 = 2.0f * (float)(tid & 3), d1 = d0 + 1.0f;
        float wl0 = expf(-decay * d0), wr0 = expf(-decay * (8.0f - d0));
        float w0  = wl0 + wr0 + 1e-12f;
        float wl1 = expf(-decay * d1), wr1 = expf(-decay * (8.0f - d1));
        float w1  = wl1 + wr1 + 1e-12f;
        unsigned long long c0x2 = pack2(wl0 / w0, wl0 / w0);
        unsigned long long c1x2 = pack2(wr0 / w0, wr0 / w0);
        unsigned long long c2x2 = pack2(wl1 / w1, wl1 / w1);
        unsigned long long c3x2 = pack2(wr1 / w1, wr1 / w1);

        // Branch-free hot loop. Taps straight from global: segment t>>2,
        // stride 256 -> +64 segments. 4 lanes share each address.
        const unsigned long long* hp =
            (const unsigned long long*)(Hrow + (tid >> 2));
        float4* op = orow + tid;
        #pragma unroll 4
        for (int t = tid; t < tailt; t += 256) {
            unsigned long long y0 = __ldg(hp);       // (H[s].x, H[s].y)
            unsigned long long y1 = __ldg(hp + 1);   // (H[s+1].x, H[s+1].y)
            unsigned long long vxy = fma_f32x2(c1x2, y1, mul_f32x2(c0x2, y0));
            unsigned long long vzw = fma_f32x2(c3x2, y1, mul_f32x2(c2x2, y0));
            float2 a = unpack2(vxy), d = unpack2(vzw);
            __stcs(op, make_float4(a.x, a.y, d.x, d.y));
            hp += 64;
            op += 256;
        }

        // Tail: freqs beyond the last pilot (right extrapolation).
        float fl   = (float)li;
        float fend = (float)(Nfft - 1);
        float u    = (fend - fl) * 0.125f;        // /(fl - (fl-8))
        float2 hA  = __ldg(Hrow + NP - 2);
        float2 hB  = __ldg(Hrow + NP - 1);
        for (int t = tailt + tid; t < nf4; t += 256) {
            float fi0 = 2.0f * (float)t, fi1 = fi0 + 1.0f;
            float wlA = expf(-decay * (fi0 - fl));
            float wrA = expf(-decay * (fend - fi0));
            float wA  = wlA + wrA + 1e-12f;
            float alA = wlA / wA, arA = wrA / wA;
            float cA1 = alA + arA * (1.0f + u);   // * H[NP-1]
            float cA0 = -arA * u;                 // * H[NP-2]
            float wlB = expf(-decay * (fi1 - fl));
            float wrB = expf(-decay * (fend - fi1));
            float wB  = wlB + wrB + 1e-12f;
            float alB = wlB / wB, arB = wrB / wB;
            float cB1 = alB + arB * (1.0f + u);
            float cB0 = -arB * u;
            float4 v;
            v.x = cA0 * hA.x + cA1 * hB.x;
            v.y = cA0 * hA.y + cA1 * hB.y;
            v.z = cB0 * hA.x + cB1 * hB.x;
            v.w = cB0 * hA.y + cB1 * hB.y;
            __stcs(orow + t, v);
        }
    } else {
        // Generic fallback: stage extended knots, per-output binary search.
        for (int k = tid; k < NP; k += 256)
            sLoc[k + 1] = __ldg(pilot_pos + k) - 1.0f;
        if (tid == 0) {
            sLoc[0]      = 0.0f;
            sLoc[NP + 1] = (float)(Nfft - 1);
        }
        __syncthreads();   // block-uniform branch: safe

        for (int t = tid; t < nf4; t += 256) {
            float4 v;
            float* vp = (float*)&v;
            #pragma unroll
            for (int h = 0; h < 2; ++h) {
                float fi = (float)(2 * t + h);
                int lo = 0, hi2 = NP + 2;
                while (lo < hi2) {
                    int mid = (lo + hi2) >> 1;
                    if (sLoc[mid] <= fi) lo = mid + 1; else hi2 = mid;
                }
                int left = lo - 1;
                if (left < 0)  left = 0;
                if (left > NP) left = NP;
                float x0 = sLoc[left], x1 = sLoc[left + 1];
                float wl = expf(-decay * fabsf(fi - x0));
                float wr = expf(-decay * fabsf(x1 - fi));
                float w  = wl + wr + 1e-12f;
                float al = wl / w, ar = wr / w;
                float c0, c1;
                int base;
                if (left == 0) {
                    float l0 = sLoc[1], l1 = sLoc[2];
                    float tt = l0 / (l1 - l0);
                    base = 0;
                    c0 = al * (1.0f + tt) + ar;
                    c1 = -al * tt;
                } else if (left == NP) {
                    float lN1 = sLoc[NP], lN2 = sLoc[NP - 1];
                    float uu = ((float)(Nfft - 1) - lN1) / (lN1 - lN2);
                    base = NP - 2;
                    c0 = -ar * uu;
                    c1 = al + ar * (1.0f + uu);
                } else {
                    base = left - 1;
                    c0 = al;
                    c1 = ar;
                }
                float2 y0 = __ldg(Hrow + base);
                float2 y1 = __ldg(Hrow + base + 1);
                vp[2 * h + 0] = c0 * y0.x + c1 * y1.x;
                vp[2 * h + 1] = c0 * y0.y + c1 * y1.y;
            }
            __stcs(orow + t, v);
        }
    }
}

extern "C" void kernel_launch(void* const* d_in, const int* in_sizes, int n_in,
                              void* d_out, int out_size) {
    const float* LS_ri       = (const float*)d_in[0];  // [B, NP, 2]
    const float* pilot_pos   = (const float*)d_in[1];  // [NP]
    const float* decay_param = (const float*)d_in[2];  // [1]
    int NP   = in_sizes[1];
    int B    = in_sizes[0] / (NP * 2);
    int Nfft = out_size / (B * 2);
    int nf4  = Nfft / 2;

    size_t smem = (size_t)(NP + 2) * sizeof(float);   // fallback knots only
    interp_kernel<<<B, 256, smem>>>((const float2*)LS_ri, pilot_pos,
                                    decay_param, (float*)d_out,
                                    NP, nf4, Nfft);
}